// round 1
// baseline (speedup 1.0000x reference)
#include <cuda_runtime.h>
#include <math.h>

#define NEGV (-1e30f)

// ---------------- static device scratch (no allocs allowed) ----------------
#define MAXMN (16384L * 2048L)
__device__ float g_D0[MAXMN];
__device__ float g_D1[MAXMN];
__device__ float g_D2[MAXMN];
__device__ float g_D3[MAXMN];
__device__ float g_D4[MAXMN];
__device__ float g_D5[MAXMN];
__device__ float g_S[64L * 256 * 256];
__device__ float g_cn1[64 * 256];
__device__ float g_cn2[64 * 256];

enum { A_N = 0, A_T = 1, A_CN = 2 };
enum { EPI_STORE = 0, EPI_ACCUM = 1, EPI_MASK = 2, EPI_BIAS = 3, EPI_BIAS_RELU = 4 };

// ---------------------------------------------------------------------------
// Generic tiled fp32 GEMM: C[b] = op(A[b]) @ op(B[b]) (+bias)(+relu)(+=C)(mask)
// BM=BN=128, BK=8, 256 threads, 8x8 per-thread tile, double-buffered smem.
// AOP: A_N normal [M,K]; A_T physical [K,M]; A_CN normal with per-k recip scale.
// BT:  0 -> B physical [K,N]; 1 -> B physical [N,K] (i.e. B^T).
// All of M,N divisible by 128 and K divisible by 8 (guaranteed by shapes).
// ---------------------------------------------------------------------------
template <int AOP, int BT, int EPI>
__global__ __launch_bounds__(256, 2) void gemm_k(
    const float* __restrict__ A, const float* __restrict__ B,
    float* __restrict__ C, int M, int N, int K,
    long sA, long sB, long sC,
    const float* __restrict__ bias, const float* __restrict__ cn,
    const int* __restrict__ n1p, const int* __restrict__ n2p)
{
    const int tid = threadIdx.x;
    const int bz  = blockIdx.z;
    const int m0  = blockIdx.y << 7;
    const int n0  = blockIdx.x << 7;

    const float* Ab = A + (long)bz * sA;
    const float* Bb = B + (long)bz * sB;
    float*       Cb = C + (long)bz * sC;

    __shared__ float As[2][8][128];
    __shared__ float Bs[2][8][128];

    // load-index precompute
    const int a_row = tid >> 1, a_kg = tid & 1;   // AOP N / CN: float4 along K
    const int a_k   = tid >> 5, a_mg = tid & 31;  // AOP T: float4 along M
    const int b_k   = tid >> 5, b_ng = tid & 31;  // BT=0: float4 along N
    const int b_row = tid >> 1, b_kg = tid & 1;   // BT=1: float4 along K

    float4 ra, rb, rc;
    rc.x = rc.y = rc.z = rc.w = 1.f;

#define LOADG(k0)                                                                    \
    do {                                                                             \
        if (AOP == A_T) {                                                            \
            ra = *(const float4*)(Ab + (long)((k0) + a_k) * M + m0 + (a_mg << 2));   \
        } else {                                                                     \
            ra = *(const float4*)(Ab + (long)(m0 + a_row) * K + (k0) + (a_kg << 2)); \
            if (AOP == A_CN)                                                         \
                rc = *(const float4*)(cn + (long)bz * K + (k0) + (a_kg << 2));       \
        }                                                                            \
        if (BT)                                                                      \
            rb = *(const float4*)(Bb + (long)(n0 + b_row) * K + (k0) + (b_kg << 2)); \
        else                                                                         \
            rb = *(const float4*)(Bb + (long)((k0) + b_k) * N + n0 + (b_ng << 2));   \
    } while (0)

#define STORES(buf)                                                                  \
    do {                                                                             \
        if (AOP == A_T) {                                                            \
            *(float4*)&As[buf][a_k][a_mg << 2] = ra;                                 \
        } else {                                                                     \
            float fa0 = ra.x, fa1 = ra.y, fa2 = ra.z, fa3 = ra.w;                    \
            if (AOP == A_CN) { fa0 *= rc.x; fa1 *= rc.y; fa2 *= rc.z; fa3 *= rc.w; } \
            As[buf][(a_kg << 2) + 0][a_row] = fa0;                                   \
            As[buf][(a_kg << 2) + 1][a_row] = fa1;                                   \
            As[buf][(a_kg << 2) + 2][a_row] = fa2;                                   \
            As[buf][(a_kg << 2) + 3][a_row] = fa3;                                   \
        }                                                                            \
        if (BT) {                                                                    \
            Bs[buf][(b_kg << 2) + 0][b_row] = rb.x;                                  \
            Bs[buf][(b_kg << 2) + 1][b_row] = rb.y;                                  \
            Bs[buf][(b_kg << 2) + 2][b_row] = rb.z;                                  \
            Bs[buf][(b_kg << 2) + 3][b_row] = rb.w;                                  \
        } else {                                                                     \
            *(float4*)&Bs[buf][b_k][b_ng << 2] = rb;                                 \
        }                                                                            \
    } while (0)

    const int tm0 = (tid >> 4) << 3;
    const int tn0 = (tid & 15) << 3;

    float acc[8][8];
#pragma unroll
    for (int i = 0; i < 8; i++)
#pragma unroll
        for (int j = 0; j < 8; j++) acc[i][j] = 0.f;

    const int nk = K >> 3;
    LOADG(0);
    STORES(0);
    __syncthreads();

    for (int kt = 0; kt < nk; ++kt) {
        const int cur = kt & 1;
        if (kt + 1 < nk) LOADG((kt + 1) << 3);

#pragma unroll
        for (int k = 0; k < 8; k++) {
            float av[8], bv[8];
            *(float4*)&av[0] = *(float4*)&As[cur][k][tm0];
            *(float4*)&av[4] = *(float4*)&As[cur][k][tm0 + 4];
            *(float4*)&bv[0] = *(float4*)&Bs[cur][k][tn0];
            *(float4*)&bv[4] = *(float4*)&Bs[cur][k][tn0 + 4];
#pragma unroll
            for (int i = 0; i < 8; i++)
#pragma unroll
                for (int j = 0; j < 8; j++) acc[i][j] += av[i] * bv[j];
        }
        if (kt + 1 < nk) {
            STORES(cur ^ 1);
            __syncthreads();
        }
    }

    // ---- epilogue ----
    float bvv[8];
    if (EPI == EPI_BIAS || EPI == EPI_BIAS_RELU) {
        *(float4*)&bvv[0] = *(const float4*)(bias + n0 + tn0);
        *(float4*)&bvv[4] = *(const float4*)(bias + n0 + tn0 + 4);
    }
    int r1 = 0, r2 = 0;
    if (EPI == EPI_MASK) { r1 = n1p[bz]; r2 = n2p[bz]; }

#pragma unroll
    for (int i = 0; i < 8; i++) {
        const int row = m0 + tm0 + i;
        float* cp = Cb + (long)row * N + n0 + tn0;
#pragma unroll
        for (int q = 0; q < 2; q++) {
            float4 v;
            v.x = acc[i][q * 4 + 0];
            v.y = acc[i][q * 4 + 1];
            v.z = acc[i][q * 4 + 2];
            v.w = acc[i][q * 4 + 3];
            if (EPI == EPI_BIAS || EPI == EPI_BIAS_RELU) {
                v.x += bvv[q * 4 + 0]; v.y += bvv[q * 4 + 1];
                v.z += bvv[q * 4 + 2]; v.w += bvv[q * 4 + 3];
            }
            if (EPI == EPI_BIAS_RELU) {
                v.x = fmaxf(v.x, 0.f); v.y = fmaxf(v.y, 0.f);
                v.z = fmaxf(v.z, 0.f); v.w = fmaxf(v.w, 0.f);
            }
            if (EPI == EPI_ACCUM) {
                float4 o = *(float4*)(cp + q * 4);
                v.x += o.x; v.y += o.y; v.z += o.z; v.w += o.w;
            }
            if (EPI == EPI_MASK) {
                const int c = n0 + tn0 + q * 4;
                const bool rv = row < r1;
                v.x = (rv && (c + 0) < r2) ? v.x : NEGV;
                v.y = (rv && (c + 1) < r2) ? v.y : NEGV;
                v.z = (rv && (c + 2) < r2) ? v.z : NEGV;
                v.w = (rv && (c + 3) < r2) ? v.w : NEGV;
            }
            *(float4*)(cp + q * 4) = v;
        }
    }
#undef LOADG
#undef STORES
}

// ------------------- column-sum reciprocal for A normalization -------------
__global__ void colsum_k(const float* __restrict__ A, float* __restrict__ cn)
{
    const int b = blockIdx.x, j = threadIdx.x;
    const float* Ab = A + ((long)b << 16);
    float s = 0.f;
#pragma unroll 8
    for (int i = 0; i < 256; i++) s += fabsf(Ab[i * 256 + j]);
    cn[(b << 8) + j] = 1.f / fmaxf(s, 1e-12f);
}

// ------------------- Sinkhorn row normalization (one warp per row) ---------
__global__ void sk_row(float* __restrict__ S, const int* __restrict__ n1)
{
    const int warp = (blockIdx.x * blockDim.x + threadIdx.x) >> 5;
    const int lane = threadIdx.x & 31;
    const int b = warp >> 8, i = warp & 255;
    if (i >= n1[b]) return;  // invalid rows untouched

    float4* row = (float4*)(S + (((long)(b * 256 + i)) << 8));
    float4 v0 = row[lane];
    float4 v1 = row[lane + 32];

    float m = fmaxf(fmaxf(fmaxf(v0.x, v0.y), fmaxf(v0.z, v0.w)),
                    fmaxf(fmaxf(v1.x, v1.y), fmaxf(v1.z, v1.w)));
#pragma unroll
    for (int o = 16; o; o >>= 1) m = fmaxf(m, __shfl_xor_sync(0xffffffffu, m, o));

    float s = expf(v0.x - m) + expf(v0.y - m) + expf(v0.z - m) + expf(v0.w - m)
            + expf(v1.x - m) + expf(v1.y - m) + expf(v1.z - m) + expf(v1.w - m);
#pragma unroll
    for (int o = 16; o; o >>= 1) s += __shfl_xor_sync(0xffffffffu, s, o);

    const float lse = m + logf(s);
    v0.x -= lse; v0.y -= lse; v0.z -= lse; v0.w -= lse;
    v1.x -= lse; v1.y -= lse; v1.z -= lse; v1.w -= lse;
    row[lane] = v0;
    row[lane + 32] = v1;
}

// --------- Sinkhorn column normalization (32 cols/block, rows in regs) -----
template <int FINAL>
__global__ void sk_col(float* __restrict__ S, const int* __restrict__ n2,
                       float* __restrict__ out)
{
    const int b  = blockIdx.y;
    const int tx = threadIdx.x & 31;
    const int ty = threadIdx.x >> 5;  // 0..7, rows ty*32..ty*32+31
    const int j  = (blockIdx.x << 5) + tx;

    float* base = S + ((long)b << 16);
    float v[32];
#pragma unroll
    for (int r = 0; r < 32; r++) v[r] = base[(ty * 32 + r) * 256 + j];

    float m = -3.4e38f;
#pragma unroll
    for (int r = 0; r < 32; r++) m = fmaxf(m, v[r]);

    __shared__ float red[8][32];
    red[ty][tx] = m;
    __syncthreads();
    float mt = red[0][tx];
#pragma unroll
    for (int k = 1; k < 8; k++) mt = fmaxf(mt, red[k][tx]);

    float s = 0.f;
#pragma unroll
    for (int r = 0; r < 32; r++) s += expf(v[r] - mt);
    __syncthreads();
    red[ty][tx] = s;
    __syncthreads();
    float st = red[0][tx];
#pragma unroll
    for (int k = 1; k < 8; k++) st += red[k][tx];

    const float lse = mt + logf(st);
    const bool cv = j < n2[b];

    if (FINAL) {
        float* ob = out + ((long)b << 16);
#pragma unroll
        for (int r = 0; r < 32; r++)
            ob[(ty * 32 + r) * 256 + j] = cv ? expf(v[r] - lse) : 0.f;
    } else {
        if (cv) {
#pragma unroll
            for (int r = 0; r < 32; r++) base[(ty * 32 + r) * 256 + j] = v[r] - lse;
        }
    }
}

// ---------------------------- host-side helpers ----------------------------
template <int AOP, int BT, int EPI>
static inline void G(const float* A, const float* B, float* C,
                     int M, int N, int K, int batch,
                     long sA, long sB, long sC,
                     const float* bias = nullptr, const float* cn = nullptr,
                     const int* n1 = nullptr, const int* n2 = nullptr)
{
    dim3 grid(N / 128, M / 128, batch);
    gemm_k<AOP, BT, EPI><<<grid, 256>>>(A, B, C, M, N, K, sA, sB, sC, bias, cn, n1, n2);
}

extern "C" void kernel_launch(void* const* d_in, const int* in_sizes, int n_in,
                              void* d_out, int out_size)
{
    const float* feat1   = (const float*)d_in[0];
    const float* feat2   = (const float*)d_in[1];
    const float* A1      = (const float*)d_in[2];
    const float* A2      = (const float*)d_in[3];
    const float* g0_aW   = (const float*)d_in[4];
    const float* g0_ab   = (const float*)d_in[5];
    const float* g0_uW   = (const float*)d_in[6];
    const float* g0_ub   = (const float*)d_in[7];
    const float* g1_aW   = (const float*)d_in[8];
    const float* g1_ab   = (const float*)d_in[9];
    const float* g1_uW   = (const float*)d_in[10];
    const float* g1_ub   = (const float*)d_in[11];
    const float* aff0_W  = (const float*)d_in[12];
    const float* aff1_W  = (const float*)d_in[13];
    const float* cross_W = (const float*)d_in[14];
    const float* cross_b = (const float*)d_in[15];
    const int*   n1      = (const int*)d_in[16];
    const int*   n2      = (const int*)d_in[17];
    float*       out     = (float*)d_out;

    float *D0, *D1, *D2, *D3, *D4, *D5, *S, *cn1, *cn2;
    cudaGetSymbolAddress((void**)&D0, g_D0);
    cudaGetSymbolAddress((void**)&D1, g_D1);
    cudaGetSymbolAddress((void**)&D2, g_D2);
    cudaGetSymbolAddress((void**)&D3, g_D3);
    cudaGetSymbolAddress((void**)&D4, g_D4);
    cudaGetSymbolAddress((void**)&D5, g_D5);
    cudaGetSymbolAddress((void**)&S,  g_S);
    cudaGetSymbolAddress((void**)&cn1, g_cn1);
    cudaGetSymbolAddress((void**)&cn2, g_cn2);

    const int B = 64, N = 256, IN = 1024, HID = 2048;
    const long sNN = (long)N * N;     // per-batch stride of [N,N]
    const long sNH = (long)N * HID;   // per-batch stride of [N,HID]

    // A column-sum reciprocals (Gconv normalization)
    colsum_k<<<64, 256>>>(A1, cn1);
    colsum_k<<<64, 256>>>(A2, cn2);

    // ---- layer 0 (Siamese Gconv) ----
    G<A_N, 0, EPI_BIAS_RELU>(feat1, g0_aW, D0, B * N, HID, IN, 1, 0, 0, 0, g0_ab);
    G<A_N, 0, EPI_BIAS_RELU>(feat1, g0_uW, D1, B * N, HID, IN, 1, 0, 0, 0, g0_ub);
    G<A_CN, 0, EPI_ACCUM>(A1, D0, D1, N, HID, N, B, sNN, sNH, sNH, nullptr, cn1);  // emb1

    G<A_N, 0, EPI_BIAS_RELU>(feat2, g0_aW, D0, B * N, HID, IN, 1, 0, 0, 0, g0_ab);
    G<A_N, 0, EPI_BIAS_RELU>(feat2, g0_uW, D2, B * N, HID, IN, 1, 0, 0, 0, g0_ub);
    G<A_CN, 0, EPI_ACCUM>(A2, D0, D2, N, HID, N, B, sNN, sNH, sNH, nullptr, cn2);  // emb2

    // ---- affinity 0: S = (emb1 @ aff0_W) @ emb2^T, masked to NEG ----
    G<A_N, 0, EPI_STORE>(D1, aff0_W, D3, B * N, HID, HID, 1, 0, 0, 0);
    G<A_N, 1, EPI_MASK>(D3, D2, S, N, N, HID, B, sNH, sNH, sNN, nullptr, nullptr, n1, n2);

    // ---- Sinkhorn 1 (10 iters, ends on col pass; final writes exp in place) ----
    for (int it = 0; it < 10; ++it) {
        if (!(it & 1))      sk_row<<<2048, 256>>>(S, n1);
        else if (it == 9)   sk_col<1><<<dim3(8, 64), 256>>>(S, n2, S);
        else                sk_col<0><<<dim3(8, 64), 256>>>(S, n2, nullptr);
    }

    // ---- cross-graph update ----
    // new_emb1 = emb1 @ Wtop + (S @ emb2) @ Wbot + b
    G<A_N, 0, EPI_STORE>(S, D2, D3, N, HID, N, B, sNN, sNH, sNH);
    G<A_N, 0, EPI_BIAS>(D1, cross_W, D4, B * N, HID, HID, 1, 0, 0, 0, cross_b);
    G<A_N, 0, EPI_ACCUM>(D3, cross_W + (long)HID * HID, D4, B * N, HID, HID, 1, 0, 0, 0);
    // new_emb2 = emb2 @ Wtop + (S^T @ emb1) @ Wbot + b
    G<A_T, 0, EPI_STORE>(S, D1, D3, N, HID, N, B, sNN, sNH, sNH);
    G<A_N, 0, EPI_BIAS>(D2, cross_W, D5, B * N, HID, HID, 1, 0, 0, 0, cross_b);
    G<A_N, 0, EPI_ACCUM>(D3, cross_W + (long)HID * HID, D5, B * N, HID, HID, 1, 0, 0, 0);

    // ---- layer 1 (Siamese Gconv) ----
    G<A_N, 0, EPI_BIAS_RELU>(D4, g1_aW, D0, B * N, HID, HID, 1, 0, 0, 0, g1_ab);
    G<A_N, 0, EPI_BIAS_RELU>(D4, g1_uW, D1, B * N, HID, HID, 1, 0, 0, 0, g1_ub);
    G<A_CN, 0, EPI_ACCUM>(A1, D0, D1, N, HID, N, B, sNN, sNH, sNH, nullptr, cn1);

    G<A_N, 0, EPI_BIAS_RELU>(D5, g1_aW, D0, B * N, HID, HID, 1, 0, 0, 0, g1_ab);
    G<A_N, 0, EPI_BIAS_RELU>(D5, g1_uW, D2, B * N, HID, HID, 1, 0, 0, 0, g1_ub);
    G<A_CN, 0, EPI_ACCUM>(A2, D0, D2, N, HID, N, B, sNN, sNH, sNH, nullptr, cn2);

    // ---- affinity 1 + Sinkhorn 2 -> d_out ----
    G<A_N, 0, EPI_STORE>(D1, aff1_W, D3, B * N, HID, HID, 1, 0, 0, 0);
    G<A_N, 1, EPI_MASK>(D3, D2, S, N, N, HID, B, sNH, sNH, sNN, nullptr, nullptr, n1, n2);

    for (int it = 0; it < 10; ++it) {
        if (!(it & 1))      sk_row<<<2048, 256>>>(S, n1);
        else if (it == 9)   sk_col<1><<<dim3(8, 64), 256>>>(S, n2, out);
        else                sk_col<0><<<dim3(8, 64), 256>>>(S, n2, nullptr);
    }
}

// round 3
// speedup vs baseline: 2.0466x; 2.0466x over previous
#include <cuda_runtime.h>
#include <cuda_bf16.h>
#include <math.h>
#include <stdint.h>

#define NEGV (-1e30f)

// ========================= static device scratch ============================
#define MAXMN (16384L * 2048L)
__device__ float g_D0[MAXMN];
__device__ float g_D1[MAXMN];
__device__ float g_D2[MAXMN];
__device__ float g_D3[MAXMN];
__device__ float g_D4[MAXMN];
__device__ float g_D5[MAXMN];
__device__ float g_S[64L * 256 * 256];
__device__ float g_cn1[64 * 256];
__device__ float g_cn2[64 * 256];
// bf16 hi/lo activation buffers
__device__ __nv_bfloat16 g_H0[MAXMN];
__device__ __nv_bfloat16 g_H1[MAXMN];
__device__ __nv_bfloat16 g_H2[MAXMN];
__device__ __nv_bfloat16 g_H3[MAXMN];
// transposed weights hi/lo (29360128 elems used)
#define WT_ELEMS 29360128L
__device__ __nv_bfloat16 g_WThi[WT_ELEMS];
__device__ __nv_bfloat16 g_WTlo[WT_ELEMS];

// ============================ PTX helpers ===================================
__device__ __forceinline__ uint32_t smem_u32(const void* p) {
    uint32_t a;
    asm("{ .reg .u64 t; cvta.to.shared.u64 t, %1; cvt.u32.u64 %0, t; }" : "=r"(a) : "l"(p));
    return a;
}
__device__ __forceinline__ void cpasync16(uint32_t dst, const void* src) {
    asm volatile("cp.async.cg.shared.global [%0], [%1], 16;" :: "r"(dst), "l"(src));
}
__device__ __forceinline__ void ldm4(uint32_t* r, uint32_t a) {
    asm volatile("ldmatrix.sync.aligned.m8n8.x4.shared.b16 {%0,%1,%2,%3}, [%4];"
                 : "=r"(r[0]), "=r"(r[1]), "=r"(r[2]), "=r"(r[3]) : "r"(a));
}
#define MMA(d, a, b0, b1)                                                    \
    asm volatile(                                                            \
        "mma.sync.aligned.m16n8k16.row.col.f32.bf16.bf16.f32 "               \
        "{%0,%1,%2,%3}, {%4,%5,%6,%7}, {%8,%9}, {%0,%1,%2,%3};"              \
        : "+f"((d)[0]), "+f"((d)[1]), "+f"((d)[2]), "+f"((d)[3])             \
        : "r"((a)[0]), "r"((a)[1]), "r"((a)[2]), "r"((a)[3]),                \
          "r"(b0), "r"(b1))

// ============ tensor-core bf16x3 GEMM: C[M,2048] = A[M,K] @ W^T =============
// A: hi/lo bf16 [M,K] K-major.  B: hi/lo bf16 [2048,K] K-major (pre-transposed
// weights).  CTA tile 128x128, K-step 32, 8 warps of 64x32, 2-stage cp.async.
enum { TC_STORE = 0, TC_BIAS = 1, TC_BIAS_RELU = 2, TC_ACCUM = 3 };

// smem stage: Ahi[128][40] Alo Bhi Blo, each 10240 B -> 40960 B; 2 stages.
#define MM_STAGE 40960
#define MM_SMEM (2 * MM_STAGE)

template <int EPI>
__global__ __launch_bounds__(256, 2) void gemm_mma(
    const __nv_bfloat16* __restrict__ Ahi, const __nv_bfloat16* __restrict__ Alo,
    const __nv_bfloat16* __restrict__ Bhi, const __nv_bfloat16* __restrict__ Blo,
    float* __restrict__ C, const float* __restrict__ bias, int K, int ldN)
{
    extern __shared__ char smem[];
    const uint32_t sb = smem_u32(smem);
    const int tid = threadIdx.x;
    const int wid = tid >> 5, lane = tid & 31;
    const int wm = wid >> 2, wn = wid & 3;  // 2 x 4 warps -> 64x32 tiles
    const int m0 = blockIdx.y << 7;
    const int n0 = blockIdx.x << 7;
    const int NC = K >> 5;

#define LOADSTAGE(c)                                                         \
    do {                                                                     \
        const uint32_t st_ = sb + (((c) & 1) ? MM_STAGE : 0);                \
        const int kc_ = (c) << 5;                                            \
        _Pragma("unroll")                                                    \
        for (int j_ = 0; j_ < 2; ++j_) {                                     \
            const int i_ = tid + j_ * 256;                                   \
            const int r_ = i_ >> 2, cg_ = i_ & 3;                            \
            const uint32_t so_ = r_ * 80 + cg_ * 16;                         \
            const long goA_ = (long)(m0 + r_) * K + kc_ + cg_ * 8;           \
            cpasync16(st_ + so_, Ahi + goA_);                                \
            cpasync16(st_ + 10240 + so_, Alo + goA_);                        \
            const long goB_ = (long)(n0 + r_) * K + kc_ + cg_ * 8;           \
            cpasync16(st_ + 20480 + so_, Bhi + goB_);                        \
            cpasync16(st_ + 30720 + so_, Blo + goB_);                        \
        }                                                                    \
        asm volatile("cp.async.commit_group;" ::: "memory");                 \
    } while (0)

    float acc[4][4][4];
#pragma unroll
    for (int a = 0; a < 4; a++)
#pragma unroll
        for (int b = 0; b < 4; b++)
#pragma unroll
            for (int c = 0; c < 4; c++) acc[a][b][c] = 0.f;

    LOADSTAGE(0);
    if (NC > 1) LOADSTAGE(1);

    for (int c = 0; c < NC; ++c) {
        if (c + 1 < NC) asm volatile("cp.async.wait_group 1;" ::: "memory");
        else            asm volatile("cp.async.wait_group 0;" ::: "memory");
        __syncthreads();

        const uint32_t st = sb + ((c & 1) ? MM_STAGE : 0);
        // lane-address bases: lanes 0-15 -> rows +0..15 col k, 16-31 -> col k+8
        const uint32_t aA = st + (uint32_t)(wm * 64 * 80 + (lane & 15) * 80 + (lane >> 4) * 16);
        const uint32_t aB = st + 20480u + (uint32_t)(wn * 32 * 80 + (lane & 15) * 80 + (lane >> 4) * 16);

#pragma unroll
        for (int kk = 0; kk < 2; ++kk) {  // k offsets 0, 16 (bytes 0, 32)
            uint32_t bh[8], bl[8];
#pragma unroll
            for (int g = 0; g < 2; ++g) {
                ldm4(&bh[g * 4], aB + g * (16 * 80) + kk * 32);
                ldm4(&bl[g * 4], aB + 10240 + g * (16 * 80) + kk * 32);
            }
#pragma unroll
            for (int mt = 0; mt < 4; ++mt) {
                uint32_t ah[4], al[4];
                ldm4(ah, aA + mt * (16 * 80) + kk * 32);
                ldm4(al, aA + 10240 + mt * (16 * 80) + kk * 32);
#pragma unroll
                for (int nt = 0; nt < 4; ++nt) {
                    const int g = nt >> 1, o = nt & 1;
                    const uint32_t b0h = bh[g * 4 + o], b1h = bh[g * 4 + 2 + o];
                    const uint32_t b0l = bl[g * 4 + o], b1l = bl[g * 4 + 2 + o];
                    MMA(acc[mt][nt], ah, b0h, b1h);
                    MMA(acc[mt][nt], ah, b0l, b1l);
                    MMA(acc[mt][nt], al, b0h, b1h);
                }
            }
        }
        __syncthreads();
        if (c + 2 < NC) LOADSTAGE(c + 2);
    }
#undef LOADSTAGE

    // ---- epilogue ----
    const int r_l = lane >> 2, c_l = (lane & 3) * 2;
    const int cb = n0 + wn * 32 + c_l;
#pragma unroll
    for (int mt = 0; mt < 4; ++mt) {
#pragma unroll
        for (int h = 0; h < 2; ++h) {
            const int row = m0 + wm * 64 + mt * 16 + h * 8 + r_l;
            float* cp = C + (long)row * ldN + cb;
#pragma unroll
            for (int nt = 0; nt < 4; ++nt) {
                float2 v;
                v.x = acc[mt][nt][h * 2 + 0];
                v.y = acc[mt][nt][h * 2 + 1];
                if (EPI == TC_BIAS || EPI == TC_BIAS_RELU) {
                    v.x += bias[cb + nt * 8];
                    v.y += bias[cb + nt * 8 + 1];
                }
                if (EPI == TC_BIAS_RELU) {
                    v.x = fmaxf(v.x, 0.f);
                    v.y = fmaxf(v.y, 0.f);
                }
                if (EPI == TC_ACCUM) {
                    const float2 o = *(float2*)(cp + nt * 8);
                    v.x += o.x;
                    v.y += o.y;
                }
                *(float2*)(cp + nt * 8) = v;
            }
        }
    }
}

// =================== fp32 -> bf16 hi/lo split (activations) =================
__global__ void split_k(const float* __restrict__ x, __nv_bfloat16* __restrict__ hi,
                        __nv_bfloat16* __restrict__ lo, long n4)
{
    const long i = (long)blockIdx.x * blockDim.x + threadIdx.x;
    if (i >= n4) return;
    const float4 v = ((const float4*)x)[i];
    const __nv_bfloat16 h0 = __float2bfloat16(v.x), h1 = __float2bfloat16(v.y);
    const __nv_bfloat16 h2 = __float2bfloat16(v.z), h3 = __float2bfloat16(v.w);
    const __nv_bfloat16 l0 = __float2bfloat16(v.x - __bfloat162float(h0));
    const __nv_bfloat16 l1 = __float2bfloat16(v.y - __bfloat162float(h1));
    const __nv_bfloat16 l2 = __float2bfloat16(v.z - __bfloat162float(h2));
    const __nv_bfloat16 l3 = __float2bfloat16(v.w - __bfloat162float(h3));
    ((__nv_bfloat162*)hi)[i * 2 + 0] = __halves2bfloat162(h0, h1);
    ((__nv_bfloat162*)hi)[i * 2 + 1] = __halves2bfloat162(h2, h3);
    ((__nv_bfloat162*)lo)[i * 2 + 0] = __halves2bfloat162(l0, l1);
    ((__nv_bfloat162*)lo)[i * 2 + 1] = __halves2bfloat162(l2, l3);
}

// ============ weight transpose + bf16 hi/lo split: W[K,N] -> [N,K] ==========
__global__ void tconv_k(const float* __restrict__ W, __nv_bfloat16* __restrict__ hi,
                        __nv_bfloat16* __restrict__ lo, int K, int N)
{
    __shared__ float t[32][33];
    const int n0 = blockIdx.x << 5, k0 = blockIdx.y << 5;
    const int tx = threadIdx.x, ty = threadIdx.y;  // 32 x 8
#pragma unroll
    for (int r = 0; r < 4; ++r)
        t[ty + 8 * r][tx] = W[(long)(k0 + ty + 8 * r) * N + n0 + tx];
    __syncthreads();
#pragma unroll
    for (int r = 0; r < 4; ++r) {
        const float v = t[tx][ty + 8 * r];
        const __nv_bfloat16 h = __float2bfloat16(v);
        const __nv_bfloat16 l = __float2bfloat16(v - __bfloat162float(h));
        const long o = (long)(n0 + ty + 8 * r) * K + k0 + tx;
        hi[o] = h;
        lo[o] = l;
    }
}

// ===================== SIMT fp32 GEMM (batched small ops) ===================
enum { A_N = 0, A_T = 1, A_CN = 2 };
enum { EPI_STORE = 0, EPI_ACCUM = 1, EPI_MASK = 2 };

template <int AOP, int BT, int EPI>
__global__ __launch_bounds__(256, 2) void gemm_k(
    const float* __restrict__ A, const float* __restrict__ B,
    float* __restrict__ C, int M, int N, int K,
    long sA, long sB, long sC,
    const float* __restrict__ cn,
    const int* __restrict__ n1p, const int* __restrict__ n2p)
{
    const int tid = threadIdx.x;
    const int bz = blockIdx.z;
    const int m0 = blockIdx.y << 7;
    const int n0 = blockIdx.x << 7;

    const float* Ab = A + (long)bz * sA;
    const float* Bb = B + (long)bz * sB;
    float* Cb = C + (long)bz * sC;

    __shared__ float As[2][8][128];
    __shared__ float Bs[2][8][128];

    const int a_row = tid >> 1, a_kg = tid & 1;
    const int a_k = tid >> 5, a_mg = tid & 31;
    const int b_k = tid >> 5, b_ng = tid & 31;
    const int b_row = tid >> 1, b_kg = tid & 1;

    float4 ra, rb, rc;
    rc.x = rc.y = rc.z = rc.w = 1.f;

#define LOADG(k0)                                                                    \
    do {                                                                             \
        if (AOP == A_T) {                                                            \
            ra = *(const float4*)(Ab + (long)((k0) + a_k) * M + m0 + (a_mg << 2));   \
        } else {                                                                     \
            ra = *(const float4*)(Ab + (long)(m0 + a_row) * K + (k0) + (a_kg << 2)); \
            if (AOP == A_CN)                                                         \
                rc = *(const float4*)(cn + (long)bz * K + (k0) + (a_kg << 2));       \
        }                                                                            \
        if (BT)                                                                      \
            rb = *(const float4*)(Bb + (long)(n0 + b_row) * K + (k0) + (b_kg << 2)); \
        else                                                                         \
            rb = *(const float4*)(Bb + (long)((k0) + b_k) * N + n0 + (b_ng << 2));   \
    } while (0)

#define STORES(buf)                                                                  \
    do {                                                                             \
        if (AOP == A_T) {                                                            \
            *(float4*)&As[buf][a_k][a_mg << 2] = ra;                                 \
        } else {                                                                     \
            float fa0 = ra.x, fa1 = ra.y, fa2 = ra.z, fa3 = ra.w;                    \
            if (AOP == A_CN) { fa0 *= rc.x; fa1 *= rc.y; fa2 *= rc.z; fa3 *= rc.w; } \
            As[buf][(a_kg << 2) + 0][a_row] = fa0;                                   \
            As[buf][(a_kg << 2) + 1][a_row] = fa1;                                   \
            As[buf][(a_kg << 2) + 2][a_row] = fa2;                                   \
            As[buf][(a_kg << 2) + 3][a_row] = fa3;                                   \
        }                                                                            \
        if (BT) {                                                                    \
            Bs[buf][(b_kg << 2) + 0][b_row] = rb.x;                                  \
            Bs[buf][(b_kg << 2) + 1][b_row] = rb.y;                                  \
            Bs[buf][(b_kg << 2) + 2][b_row] = rb.z;                                  \
            Bs[buf][(b_kg << 2) + 3][b_row] = rb.w;                                  \
        } else {                                                                     \
            *(float4*)&Bs[buf][b_k][b_ng << 2] = rb;                                 \
        }                                                                            \
    } while (0)

    const int tm0 = (tid >> 4) << 3;
    const int tn0 = (tid & 15) << 3;

    float acc[8][8];
#pragma unroll
    for (int i = 0; i < 8; i++)
#pragma unroll
        for (int j = 0; j < 8; j++) acc[i][j] = 0.f;

    const int nk = K >> 3;
    LOADG(0);
    STORES(0);
    __syncthreads();

    for (int kt = 0; kt < nk; ++kt) {
        const int cur = kt & 1;
        if (kt + 1 < nk) LOADG((kt + 1) << 3);

#pragma unroll
        for (int k = 0; k < 8; k++) {
            float av[8], bv[8];
            *(float4*)&av[0] = *(float4*)&As[cur][k][tm0];
            *(float4*)&av[4] = *(float4*)&As[cur][k][tm0 + 4];
            *(float4*)&bv[0] = *(float4*)&Bs[cur][k][tn0];
            *(float4*)&bv[4] = *(float4*)&Bs[cur][k][tn0 + 4];
#pragma unroll
            for (int i = 0; i < 8; i++)
#pragma unroll
                for (int j = 0; j < 8; j++) acc[i][j] += av[i] * bv[j];
        }
        if (kt + 1 < nk) {
            STORES(cur ^ 1);
            __syncthreads();
        }
    }

    int r1 = 0, r2 = 0;
    if (EPI == EPI_MASK) { r1 = n1p[bz]; r2 = n2p[bz]; }

#pragma unroll
    for (int i = 0; i < 8; i++) {
        const int row = m0 + tm0 + i;
        float* cp = Cb + (long)row * N + n0 + tn0;
#pragma unroll
        for (int q = 0; q < 2; q++) {
            float4 v;
            v.x = acc[i][q * 4 + 0];
            v.y = acc[i][q * 4 + 1];
            v.z = acc[i][q * 4 + 2];
            v.w = acc[i][q * 4 + 3];
            if (EPI == EPI_ACCUM) {
                float4 o = *(float4*)(cp + q * 4);
                v.x += o.x; v.y += o.y; v.z += o.z; v.w += o.w;
            }
            if (EPI == EPI_MASK) {
                const int c = n0 + tn0 + q * 4;
                const bool rv = row < r1;
                v.x = (rv && (c + 0) < r2) ? v.x : NEGV;
                v.y = (rv && (c + 1) < r2) ? v.y : NEGV;
                v.z = (rv && (c + 2) < r2) ? v.z : NEGV;
                v.w = (rv && (c + 3) < r2) ? v.w : NEGV;
            }
            *(float4*)(cp + q * 4) = v;
        }
    }
#undef LOADG
#undef STORES
}

// ------------------- column-sum reciprocal for A normalization -------------
__global__ void colsum_k(const float* __restrict__ A, float* __restrict__ cn)
{
    const int b = blockIdx.x, j = threadIdx.x;
    const float* Ab = A + ((long)b << 16);
    float s = 0.f;
#pragma unroll 8
    for (int i = 0; i < 256; i++) s += fabsf(Ab[i * 256 + j]);
    cn[(b << 8) + j] = 1.f / fmaxf(s, 1e-12f);
}

// ------------------- Sinkhorn row normalization (one warp per row) ---------
__global__ void sk_row(float* __restrict__ S, const int* __restrict__ n1)
{
    const int warp = (blockIdx.x * blockDim.x + threadIdx.x) >> 5;
    const int lane = threadIdx.x & 31;
    const int b = warp >> 8, i = warp & 255;
    if (i >= n1[b]) return;

    float4* row = (float4*)(S + (((long)(b * 256 + i)) << 8));
    float4 v0 = row[lane];
    float4 v1 = row[lane + 32];

    float m = fmaxf(fmaxf(fmaxf(v0.x, v0.y), fmaxf(v0.z, v0.w)),
                    fmaxf(fmaxf(v1.x, v1.y), fmaxf(v1.z, v1.w)));
#pragma unroll
    for (int o = 16; o; o >>= 1) m = fmaxf(m, __shfl_xor_sync(0xffffffffu, m, o));

    float s = expf(v0.x - m) + expf(v0.y - m) + expf(v0.z - m) + expf(v0.w - m)
            + expf(v1.x - m) + expf(v1.y - m) + expf(v1.z - m) + expf(v1.w - m);
#pragma unroll
    for (int o = 16; o; o >>= 1) s += __shfl_xor_sync(0xffffffffu, s, o);

    const float lse = m + logf(s);
    v0.x -= lse; v0.y -= lse; v0.z -= lse; v0.w -= lse;
    v1.x -= lse; v1.y -= lse; v1.z -= lse; v1.w -= lse;
    row[lane] = v0;
    row[lane + 32] = v1;
}

// --------- Sinkhorn column normalization (32 cols/block, rows in regs) -----
template <int FINAL>
__global__ void sk_col(float* __restrict__ S, const int* __restrict__ n2,
                       float* __restrict__ out)
{
    const int b = blockIdx.y;
    const int tx = threadIdx.x & 31;
    const int ty = threadIdx.x >> 5;
    const int j = (blockIdx.x << 5) + tx;

    float* base = S + ((long)b << 16);
    float v[32];
#pragma unroll
    for (int r = 0; r < 32; r++) v[r] = base[(ty * 32 + r) * 256 + j];

    float m = -3.4e38f;
#pragma unroll
    for (int r = 0; r < 32; r++) m = fmaxf(m, v[r]);

    __shared__ float red[8][32];
    red[ty][tx] = m;
    __syncthreads();
    float mt = red[0][tx];
#pragma unroll
    for (int k = 1; k < 8; k++) mt = fmaxf(mt, red[k][tx]);

    float s = 0.f;
#pragma unroll
    for (int r = 0; r < 32; r++) s += expf(v[r] - mt);
    __syncthreads();
    red[ty][tx] = s;
    __syncthreads();
    float st = red[0][tx];
#pragma unroll
    for (int k = 1; k < 8; k++) st += red[k][tx];

    const float lse = mt + logf(st);
    const bool cv = j < n2[b];

    if (FINAL) {
        float* ob = out + ((long)b << 16);
#pragma unroll
        for (int r = 0; r < 32; r++)
            ob[(ty * 32 + r) * 256 + j] = cv ? expf(v[r] - lse) : 0.f;
    } else {
        if (cv) {
#pragma unroll
            for (int r = 0; r < 32; r++) base[(ty * 32 + r) * 256 + j] = v[r] - lse;
        }
    }
}

// ---------------------------- host-side helpers ----------------------------
template <int AOP, int BT, int EPI>
static inline void G(const float* A, const float* B, float* C,
                     int M, int N, int K, int batch,
                     long sA, long sB, long sC,
                     const float* cn = nullptr,
                     const int* n1 = nullptr, const int* n2 = nullptr)
{
    dim3 grid(N / 128, M / 128, batch);
    gemm_k<AOP, BT, EPI><<<grid, 256>>>(A, B, C, M, N, K, sA, sB, sC, cn, n1, n2);
}

template <int EPI>
static inline void GT(const __nv_bfloat16* Ahi, const __nv_bfloat16* Alo,
                      const __nv_bfloat16* Bthi, const __nv_bfloat16* Btlo,
                      float* C, const float* bias, int M, int K)
{
    static bool attr_done = false;
    if (!attr_done) {
        cudaFuncSetAttribute(gemm_mma<EPI>, cudaFuncAttributeMaxDynamicSharedMemorySize, MM_SMEM);
        attr_done = true;
    }
    dim3 grid(2048 / 128, M / 128);
    gemm_mma<EPI><<<grid, 256, MM_SMEM>>>(Ahi, Alo, Bthi, Btlo, C, bias, K, 2048);
}

static inline void SPLIT(const float* x, __nv_bfloat16* hi, __nv_bfloat16* lo, long n)
{
    const long n4 = n >> 2;
    split_k<<<(unsigned)((n4 + 255) / 256), 256>>>(x, hi, lo, n4);
}

static inline void TCONV(const float* W, __nv_bfloat16* hi, __nv_bfloat16* lo, int K, int N)
{
    dim3 grid(N / 32, K / 32);
    tconv_k<<<grid, dim3(32, 8)>>>(W, hi, lo, K, N);
}

extern "C" void kernel_launch(void* const* d_in, const int* in_sizes, int n_in,
                              void* d_out, int out_size)
{
    const float* feat1   = (const float*)d_in[0];
    const float* feat2   = (const float*)d_in[1];
    const float* A1      = (const float*)d_in[2];
    const float* A2      = (const float*)d_in[3];
    const float* g0_aW   = (const float*)d_in[4];
    const float* g0_ab   = (const float*)d_in[5];
    const float* g0_uW   = (const float*)d_in[6];
    const float* g0_ub   = (const float*)d_in[7];
    const float* g1_aW   = (const float*)d_in[8];
    const float* g1_ab   = (const float*)d_in[9];
    const float* g1_uW   = (const float*)d_in[10];
    const float* g1_ub   = (const float*)d_in[11];
    const float* aff0_W  = (const float*)d_in[12];
    const float* aff1_W  = (const float*)d_in[13];
    const float* cross_W = (const float*)d_in[14];
    const float* cross_b = (const float*)d_in[15];
    const int*   n1      = (const int*)d_in[16];
    const int*   n2      = (const int*)d_in[17];
    float*       out     = (float*)d_out;

    float *D0, *D1, *D2, *D3, *D4, *D5, *S, *cn1, *cn2;
    __nv_bfloat16 *H0, *H1, *H2, *H3, *WThi, *WTlo;
    cudaGetSymbolAddress((void**)&D0, g_D0);
    cudaGetSymbolAddress((void**)&D1, g_D1);
    cudaGetSymbolAddress((void**)&D2, g_D2);
    cudaGetSymbolAddress((void**)&D3, g_D3);
    cudaGetSymbolAddress((void**)&D4, g_D4);
    cudaGetSymbolAddress((void**)&D5, g_D5);
    cudaGetSymbolAddress((void**)&S, g_S);
    cudaGetSymbolAddress((void**)&cn1, g_cn1);
    cudaGetSymbolAddress((void**)&cn2, g_cn2);
    cudaGetSymbolAddress((void**)&H0, g_H0);
    cudaGetSymbolAddress((void**)&H1, g_H1);
    cudaGetSymbolAddress((void**)&H2, g_H2);
    cudaGetSymbolAddress((void**)&H3, g_H3);
    cudaGetSymbolAddress((void**)&WThi, g_WThi);
    cudaGetSymbolAddress((void**)&WTlo, g_WTlo);

    const int B = 64, N = 256, IN = 1024, HID = 2048;
    const long sNN = (long)N * N;
    const long sNH = (long)N * HID;
    const long M = (long)B * N;  // 16384

    // transposed-weight offsets (elements)
    const long o_g0a = 0, o_g0u = 2097152, o_g1a = 4194304, o_g1u = 8388608;
    const long o_af0 = 12582912, o_af1 = 16777216, o_cT = 20971520, o_cB = 25165824;

    // ---- weight prep (transpose + hi/lo split) ----
    TCONV(g0_aW, WThi + o_g0a, WTlo + o_g0a, IN, HID);
    TCONV(g0_uW, WThi + o_g0u, WTlo + o_g0u, IN, HID);
    TCONV(g1_aW, WThi + o_g1a, WTlo + o_g1a, HID, HID);
    TCONV(g1_uW, WThi + o_g1u, WTlo + o_g1u, HID, HID);
    TCONV(aff0_W, WThi + o_af0, WTlo + o_af0, HID, HID);
    TCONV(aff1_W, WThi + o_af1, WTlo + o_af1, HID, HID);
    TCONV(cross_W, WThi + o_cT, WTlo + o_cT, HID, HID);
    TCONV(cross_W + (long)HID * HID, WThi + o_cB, WTlo + o_cB, HID, HID);

    colsum_k<<<64, 256>>>(A1, cn1);
    colsum_k<<<64, 256>>>(A2, cn2);

    // ---- layer 0 (Siamese Gconv) ----
    SPLIT(feat1, H0, H1, M * IN);
    GT<TC_BIAS_RELU>(H0, H1, WThi + o_g0a, WTlo + o_g0a, D0, g0_ab, (int)M, IN);
    GT<TC_BIAS_RELU>(H0, H1, WThi + o_g0u, WTlo + o_g0u, D1, g0_ub, (int)M, IN);
    G<A_CN, 0, EPI_ACCUM>(A1, D0, D1, N, HID, N, B, sNN, sNH, sNH, cn1);  // emb1

    SPLIT(feat2, H0, H1, M * IN);
    GT<TC_BIAS_RELU>(H0, H1, WThi + o_g0a, WTlo + o_g0a, D0, g0_ab, (int)M, IN);
    GT<TC_BIAS_RELU>(H0, H1, WThi + o_g0u, WTlo + o_g0u, D2, g0_ub, (int)M, IN);
    G<A_CN, 0, EPI_ACCUM>(A2, D0, D2, N, HID, N, B, sNN, sNH, sNH, cn2);  // emb2

    // ---- affinity 0 ----
    SPLIT(D1, H0, H1, M * HID);  // emb1 hi/lo (kept for cross fc)
    GT<TC_STORE>(H0, H1, WThi + o_af0, WTlo + o_af0, D3, nullptr, (int)M, HID);
    G<A_N, 1, EPI_MASK>(D3, D2, S, N, N, HID, B, sNH, sNH, sNN, nullptr, n1, n2);

    for (int it = 0; it < 10; ++it) {
        if (!(it & 1))    sk_row<<<2048, 256>>>(S, n1);
        else if (it == 9) sk_col<1><<<dim3(8, 64), 256>>>(S, n2, S);
        else              sk_col<0><<<dim3(8, 64), 256>>>(S, n2, nullptr);
    }

    // ---- cross-graph update ----
    G<A_N, 0, EPI_STORE>(S, D2, D3, N, HID, N, B, sNN, sNH, sNH);  // S @ emb2
    SPLIT(D3, H2, H3, M * HID);
    GT<TC_BIAS>(H0, H1, WThi + o_cT, WTlo + o_cT, D4, cross_b, (int)M, HID);
    GT<TC_ACCUM>(H2, H3, WThi + o_cB, WTlo + o_cB, D4, nullptr, (int)M, HID);

    G<A_T, 0, EPI_STORE>(S, D1, D3, N, HID, N, B, sNN, sNH, sNH);  // S^T @ emb1
    SPLIT(D2, H0, H1, M * HID);
    SPLIT(D3, H2, H3, M * HID);
    GT<TC_BIAS>(H0, H1, WThi + o_cT, WTlo + o_cT, D5, cross_b, (int)M, HID);
    GT<TC_ACCUM>(H2, H3, WThi + o_cB, WTlo + o_cB, D5, nullptr, (int)M, HID);

    // ---- layer 1 (Siamese Gconv) ----
    SPLIT(D4, H0, H1, M * HID);
    GT<TC_BIAS_RELU>(H0, H1, WThi + o_g1a, WTlo + o_g1a, D0, g1_ab, (int)M, HID);
    GT<TC_BIAS_RELU>(H0, H1, WThi + o_g1u, WTlo + o_g1u, D1, g1_ub, (int)M, HID);
    G<A_CN, 0, EPI_ACCUM>(A1, D0, D1, N, HID, N, B, sNN, sNH, sNH, cn1);  // emb1'

    SPLIT(D5, H0, H1, M * HID);
    GT<TC_BIAS_RELU>(H0, H1, WThi + o_g1a, WTlo + o_g1a, D0, g1_ab, (int)M, HID);
    GT<TC_BIAS_RELU>(H0, H1, WThi + o_g1u, WTlo + o_g1u, D2, g1_ub, (int)M, HID);
    G<A_CN, 0, EPI_ACCUM>(A2, D0, D2, N, HID, N, B, sNN, sNH, sNH, cn2);  // emb2'

    // ---- affinity 1 + Sinkhorn 2 -> out ----
    SPLIT(D1, H0, H1, M * HID);
    GT<TC_STORE>(H0, H1, WThi + o_af1, WTlo + o_af1, D3, nullptr, (int)M, HID);
    G<A_N, 1, EPI_MASK>(D3, D2, S, N, N, HID, B, sNH, sNH, sNN, nullptr, n1, n2);

    for (int it = 0; it < 10; ++it) {
        if (!(it & 1))    sk_row<<<2048, 256>>>(S, n1);
        else if (it == 9) sk_col<1><<<dim3(8, 64), 256>>>(S, n2, out);
        else              sk_col<0><<<dim3(8, 64), 256>>>(S, n2, nullptr);
    }
}

// round 4
// speedup vs baseline: 2.2683x; 1.1083x over previous
#include <cuda_runtime.h>
#include <cuda_bf16.h>
#include <math.h>
#include <stdint.h>

#define NEGV (-1e30f)

// ========================= static device scratch ============================
#define MAXMN (16384L * 2048L)
// fp32 intermediates
__device__ float g_D1[MAXMN];   // ux graph1 / scratch
__device__ float g_D2[MAXMN];   // ux graph2 / scratch
__device__ float g_D4[MAXMN];   // cross top graph1
__device__ float g_D5[MAXMN];   // cross top graph2
__device__ float g_S[64L * 256 * 256];
__device__ float g_cn1[64 * 256];
__device__ float g_cn2[64 * 256];
// bf16 hi/lo pairs (activations)
__device__ __nv_bfloat16 g_P0h[MAXMN], g_P0l[MAXMN];  // fc input (feat / new_emb1)
__device__ __nv_bfloat16 g_P1h[MAXMN], g_P1l[MAXMN];  // new_emb2
__device__ __nv_bfloat16 g_XAh[MAXMN], g_XAl[MAXMN];  // ax
__device__ __nv_bfloat16 g_Xh[MAXMN],  g_Xl[MAXMN];   // generic X
__device__ __nv_bfloat16 g_E1h[MAXMN], g_E1l[MAXMN];  // emb1
__device__ __nv_bfloat16 g_E2h[MAXMN], g_E2l[MAXMN];  // emb2
// small pairs
#define SNN (64L * 256 * 256)
__device__ __nv_bfloat16 g_AN1h[SNN], g_AN1l[SNN];
__device__ __nv_bfloat16 g_AN2h[SNN], g_AN2l[SNN];
__device__ __nv_bfloat16 g_Sh[SNN],  g_Sl[SNN];
__device__ __nv_bfloat16 g_STh[SNN], g_STl[SNN];
// transposed weights hi/lo
#define WT_ELEMS 29360128L
__device__ __nv_bfloat16 g_WThi[WT_ELEMS];
__device__ __nv_bfloat16 g_WTlo[WT_ELEMS];

// ============================ PTX helpers ===================================
__device__ __forceinline__ uint32_t smem_u32(const void* p) {
    uint32_t a;
    asm("{ .reg .u64 t; cvta.to.shared.u64 t, %1; cvt.u32.u64 %0, t; }" : "=r"(a) : "l"(p));
    return a;
}
__device__ __forceinline__ void cpasync16(uint32_t dst, const void* src) {
    asm volatile("cp.async.cg.shared.global [%0], [%1], 16;" :: "r"(dst), "l"(src));
}
__device__ __forceinline__ void ldm4(uint32_t* r, uint32_t a) {
    asm volatile("ldmatrix.sync.aligned.m8n8.x4.shared.b16 {%0,%1,%2,%3}, [%4];"
                 : "=r"(r[0]), "=r"(r[1]), "=r"(r[2]), "=r"(r[3]) : "r"(a));
}
__device__ __forceinline__ void ldm4t(uint32_t* r, uint32_t a) {
    asm volatile("ldmatrix.sync.aligned.m8n8.x4.trans.shared.b16 {%0,%1,%2,%3}, [%4];"
                 : "=r"(r[0]), "=r"(r[1]), "=r"(r[2]), "=r"(r[3]) : "r"(a));
}
#define MMA(d, a, b0, b1)                                                    \
    asm volatile(                                                            \
        "mma.sync.aligned.m16n8k16.row.col.f32.bf16.bf16.f32 "               \
        "{%0,%1,%2,%3}, {%4,%5,%6,%7}, {%8,%9}, {%0,%1,%2,%3};"              \
        : "+f"((d)[0]), "+f"((d)[1]), "+f"((d)[2]), "+f"((d)[3])             \
        : "r"((a)[0]), "r"((a)[1]), "r"((a)[2]), "r"((a)[3]),                \
          "r"(b0), "r"(b1))

__device__ __forceinline__ void split_store2(__nv_bfloat16* oh, __nv_bfloat16* ol,
                                             float x, float y) {
    const __nv_bfloat16 hx = __float2bfloat16(x), hy = __float2bfloat16(y);
    const __nv_bfloat16 lx = __float2bfloat16(x - __bfloat162float(hx));
    const __nv_bfloat16 ly = __float2bfloat16(y - __bfloat162float(hy));
    *(__nv_bfloat162*)oh = __halves2bfloat162(hx, hy);
    *(__nv_bfloat162*)ol = __halves2bfloat162(lx, ly);
}

// ==================== unified tensor-core bf16x3 GEMM =======================
// C = A @ B(^T), A: hi/lo bf16 [M,K] row-major.
// BTRANS=0: B hi/lo [N,K] K-major (ldmatrix non-trans).
// BTRANS=1: B hi/lo [K,N] row-major, ldB = row stride (ldmatrix trans).
// CTA 128x128, K-step 32, 8 warps (64x32), 2-stage cp.async.
enum {
    EP_F32_BIAS = 0,
    EP_F32_BIAS_RELU = 1,
    EP_SPLIT_BIAS_RELU = 2,
    EP_SPLIT = 3,
    EP_SPLIT_ACCUM = 4,
    EP_F32_MASK = 5
};

#define MM_STAGE 40960
#define MM_SMEM (2 * MM_STAGE)

template <int BTRANS, int EPI>
__global__ __launch_bounds__(256, 2) void gmma(
    const __nv_bfloat16* __restrict__ Ah, const __nv_bfloat16* __restrict__ Al,
    const __nv_bfloat16* __restrict__ Bh, const __nv_bfloat16* __restrict__ Bl,
    float* __restrict__ Cf, __nv_bfloat16* __restrict__ Oh, __nv_bfloat16* __restrict__ Ol,
    const float* __restrict__ bias, int K, int ldB, int ldC,
    long sA, long sB, long sC,
    const int* __restrict__ n1p, const int* __restrict__ n2p)
{
    extern __shared__ char smem[];
    const uint32_t sb = smem_u32(smem);
    const int tid = threadIdx.x;
    const int wid = tid >> 5, lane = tid & 31;
    const int wm = wid >> 2, wn = wid & 3;
    const int m0 = blockIdx.y << 7;
    const int n0 = blockIdx.x << 7;
    const int bz = blockIdx.z;
    const int NC = K >> 5;

    const __nv_bfloat16* Abh = Ah + (long)bz * sA;
    const __nv_bfloat16* Abl = Al + (long)bz * sA;
    const __nv_bfloat16* Bbh = Bh + (long)bz * sB;
    const __nv_bfloat16* Bbl = Bl + (long)bz * sB;

#define LOADSTAGE(c)                                                          \
    do {                                                                      \
        const uint32_t st_ = sb + (((c) & 1) ? MM_STAGE : 0);                 \
        const int kc_ = (c) << 5;                                             \
        _Pragma("unroll")                                                     \
        for (int j_ = 0; j_ < 2; ++j_) {                                      \
            const int i_ = tid + j_ * 256;                                    \
            const int r_ = i_ >> 2, cg_ = i_ & 3;                             \
            const uint32_t so_ = r_ * 80 + cg_ * 16;                          \
            const long goA_ = (long)(m0 + r_) * K + kc_ + cg_ * 8;            \
            cpasync16(st_ + so_, Abh + goA_);                                 \
            cpasync16(st_ + 10240 + so_, Abl + goA_);                         \
        }                                                                     \
        if (BTRANS) {                                                         \
            _Pragma("unroll")                                                 \
            for (int j_ = 0; j_ < 2; ++j_) {                                  \
                const int i_ = tid + j_ * 256;                                \
                const int r_ = i_ >> 4, ch_ = i_ & 15;                        \
                const uint32_t so_ = r_ * 272 + ch_ * 16;                     \
                const long goB_ = (long)(kc_ + r_) * ldB + n0 + ch_ * 8;      \
                cpasync16(st_ + 20480 + so_, Bbh + goB_);                     \
                cpasync16(st_ + 29184 + so_, Bbl + goB_);                     \
            }                                                                 \
        } else {                                                              \
            _Pragma("unroll")                                                 \
            for (int j_ = 0; j_ < 2; ++j_) {                                  \
                const int i_ = tid + j_ * 256;                                \
                const int r_ = i_ >> 2, cg_ = i_ & 3;                         \
                const uint32_t so_ = r_ * 80 + cg_ * 16;                      \
                const long goB_ = (long)(n0 + r_) * K + kc_ + cg_ * 8;        \
                cpasync16(st_ + 20480 + so_, Bbh + goB_);                     \
                cpasync16(st_ + 30720 + so_, Bbl + goB_);                     \
            }                                                                 \
        }                                                                     \
        asm volatile("cp.async.commit_group;" ::: "memory");                  \
    } while (0)

    float acc[4][4][4];
#pragma unroll
    for (int a = 0; a < 4; a++)
#pragma unroll
        for (int b = 0; b < 4; b++)
#pragma unroll
            for (int c = 0; c < 4; c++) acc[a][b][c] = 0.f;

    LOADSTAGE(0);
    if (NC > 1) LOADSTAGE(1);

    for (int c = 0; c < NC; ++c) {
        if (c + 1 < NC) asm volatile("cp.async.wait_group 1;" ::: "memory");
        else            asm volatile("cp.async.wait_group 0;" ::: "memory");
        __syncthreads();

        const uint32_t st = sb + ((c & 1) ? MM_STAGE : 0);
        const uint32_t aA = st + (uint32_t)(wm * 64 * 80 + (lane & 15) * 80 + (lane >> 4) * 16);

#pragma unroll
        for (int kk = 0; kk < 2; ++kk) {
            uint32_t bh[8], bl[8];
            if (BTRANS) {
#pragma unroll
                for (int g = 0; g < 2; ++g) {
                    const uint32_t ro = (uint32_t)(kk * 16 + (lane & 7) + ((lane >> 4) << 3)) * 272;
                    const uint32_t co = (uint32_t)(wn * 32 + g * 16 + (((lane >> 3) & 1) << 3)) * 2;
                    ldm4t(&bh[g * 4], st + 20480 + ro + co);
                    ldm4t(&bl[g * 4], st + 29184 + ro + co);
                }
            } else {
                const uint32_t aB = st + 20480u +
                    (uint32_t)(wn * 32 * 80 + (lane & 15) * 80 + (lane >> 4) * 16);
#pragma unroll
                for (int g = 0; g < 2; ++g) {
                    ldm4(&bh[g * 4], aB + g * (16 * 80) + kk * 32);
                    ldm4(&bl[g * 4], aB + 10240 + g * (16 * 80) + kk * 32);
                }
            }
#pragma unroll
            for (int mt = 0; mt < 4; ++mt) {
                uint32_t ah[4], al[4];
                ldm4(ah, aA + mt * (16 * 80) + kk * 32);
                ldm4(al, aA + 10240 + mt * (16 * 80) + kk * 32);
#pragma unroll
                for (int nt = 0; nt < 4; ++nt) {
                    const int g = nt >> 1, o = nt & 1;
                    const uint32_t b0h = bh[g * 4 + o], b1h = bh[g * 4 + 2 + o];
                    const uint32_t b0l = bl[g * 4 + o], b1l = bl[g * 4 + 2 + o];
                    MMA(acc[mt][nt], ah, b0h, b1h);
                    MMA(acc[mt][nt], ah, b0l, b1l);
                    MMA(acc[mt][nt], al, b0h, b1h);
                }
            }
        }
        __syncthreads();
        if (c + 2 < NC) LOADSTAGE(c + 2);
    }
#undef LOADSTAGE

    // ---- epilogue ----
    float* Cb = (Cf != nullptr) ? Cf + (long)bz * sC : nullptr;
    __nv_bfloat16* Ohb = (Oh != nullptr) ? Oh + (long)bz * sC : nullptr;
    __nv_bfloat16* Olb = (Ol != nullptr) ? Ol + (long)bz * sC : nullptr;

    const int r_l = lane >> 2, c_l = (lane & 3) * 2;
    const int cb = n0 + wn * 32 + c_l;
    int r1 = 0, r2 = 0;
    if (EPI == EP_F32_MASK) { r1 = n1p[bz]; r2 = n2p[bz]; }

#pragma unroll
    for (int mt = 0; mt < 4; ++mt) {
#pragma unroll
        for (int h = 0; h < 2; ++h) {
            const int row = m0 + wm * 64 + mt * 16 + h * 8 + r_l;
            const long rbase = (long)row * ldC;
#pragma unroll
            for (int nt = 0; nt < 4; ++nt) {
                float vx = acc[mt][nt][h * 2 + 0];
                float vy = acc[mt][nt][h * 2 + 1];
                const int col = cb + nt * 8;
                if (EPI == EP_F32_BIAS || EPI == EP_F32_BIAS_RELU || EPI == EP_SPLIT_BIAS_RELU) {
                    vx += bias[col];
                    vy += bias[col + 1];
                }
                if (EPI == EP_F32_BIAS_RELU || EPI == EP_SPLIT_BIAS_RELU) {
                    vx = fmaxf(vx, 0.f);
                    vy = fmaxf(vy, 0.f);
                }
                if (EPI == EP_SPLIT_ACCUM) {
                    const float2 o = *(const float2*)(Cb + rbase + col);
                    vx += o.x;
                    vy += o.y;
                }
                if (EPI == EP_F32_MASK) {
                    const bool rv = row < r1;
                    vx = (rv && (col + 0) < r2) ? vx : NEGV;
                    vy = (rv && (col + 1) < r2) ? vy : NEGV;
                }
                if (EPI == EP_F32_BIAS || EPI == EP_F32_BIAS_RELU || EPI == EP_F32_MASK) {
                    float2 v;
                    v.x = vx;
                    v.y = vy;
                    *(float2*)(Cb + rbase + col) = v;
                } else {
                    split_store2(Ohb + rbase + col, Olb + rbase + col, vx, vy);
                }
            }
        }
    }
}

// =================== fp32 -> bf16 hi/lo split (feat only) ===================
__global__ void split_k(const float* __restrict__ x, __nv_bfloat16* __restrict__ hi,
                        __nv_bfloat16* __restrict__ lo, long n4)
{
    const long i = (long)blockIdx.x * blockDim.x + threadIdx.x;
    if (i >= n4) return;
    const float4 v = ((const float4*)x)[i];
    __nv_bfloat16 h0 = __float2bfloat16(v.x), h1 = __float2bfloat16(v.y);
    __nv_bfloat16 h2 = __float2bfloat16(v.z), h3 = __float2bfloat16(v.w);
    __nv_bfloat16 l0 = __float2bfloat16(v.x - __bfloat162float(h0));
    __nv_bfloat16 l1 = __float2bfloat16(v.y - __bfloat162float(h1));
    __nv_bfloat16 l2 = __float2bfloat16(v.z - __bfloat162float(h2));
    __nv_bfloat16 l3 = __float2bfloat16(v.w - __bfloat162float(h3));
    ((__nv_bfloat162*)hi)[i * 2 + 0] = __halves2bfloat162(h0, h1);
    ((__nv_bfloat162*)hi)[i * 2 + 1] = __halves2bfloat162(h2, h3);
    ((__nv_bfloat162*)lo)[i * 2 + 0] = __halves2bfloat162(l0, l1);
    ((__nv_bfloat162*)lo)[i * 2 + 1] = __halves2bfloat162(l2, l3);
}

// ============ weight transpose + bf16 hi/lo split: W[K,N] -> [N,K] ==========
__global__ void tconv_k(const float* __restrict__ W, __nv_bfloat16* __restrict__ hi,
                        __nv_bfloat16* __restrict__ lo, int K, int N)
{
    __shared__ float t[32][33];
    const int n0 = blockIdx.x << 5, k0 = blockIdx.y << 5;
    const int tx = threadIdx.x, ty = threadIdx.y;
#pragma unroll
    for (int r = 0; r < 4; ++r)
        t[ty + 8 * r][tx] = W[(long)(k0 + ty + 8 * r) * N + n0 + tx];
    __syncthreads();
#pragma unroll
    for (int r = 0; r < 4; ++r) {
        const float v = t[tx][ty + 8 * r];
        const __nv_bfloat16 h = __float2bfloat16(v);
        const __nv_bfloat16 l = __float2bfloat16(v - __bfloat162float(h));
        const long o = (long)(n0 + ty + 8 * r) * K + k0 + tx;
        hi[o] = h;
        lo[o] = l;
    }
}

// ---------- column-sum reciprocal + normalized-A bf16 split -----------------
__global__ void colsum_k(const float* __restrict__ A, float* __restrict__ cn)
{
    const int b = blockIdx.x, j = threadIdx.x;
    const float* Ab = A + ((long)b << 16);
    float s = 0.f;
#pragma unroll 8
    for (int i = 0; i < 256; i++) s += fabsf(Ab[i * 256 + j]);
    cn[(b << 8) + j] = 1.f / fmaxf(s, 1e-12f);
}

__global__ void ansplit_k(const float* __restrict__ A, const float* __restrict__ cn,
                          __nv_bfloat16* __restrict__ hi, __nv_bfloat16* __restrict__ lo)
{
    const int b = blockIdx.x, j = threadIdx.x;
    const float c = cn[(b << 8) + j];
    const long base = (long)b << 16;
#pragma unroll 4
    for (int i = 0; i < 256; i++) {
        const float v = A[base + i * 256 + j] * c;
        const __nv_bfloat16 h = __float2bfloat16(v);
        hi[base + i * 256 + j] = h;
        lo[base + i * 256 + j] = __float2bfloat16(v - __bfloat162float(h));
    }
}

// ------------------- Sinkhorn row normalization (one warp per row) ---------
__global__ void sk_row(float* __restrict__ S, const int* __restrict__ n1)
{
    const int warp = (blockIdx.x * blockDim.x + threadIdx.x) >> 5;
    const int lane = threadIdx.x & 31;
    const int b = warp >> 8, i = warp & 255;
    if (i >= n1[b]) return;

    float4* row = (float4*)(S + (((long)(b * 256 + i)) << 8));
    float4 v0 = row[lane];
    float4 v1 = row[lane + 32];

    float m = fmaxf(fmaxf(fmaxf(v0.x, v0.y), fmaxf(v0.z, v0.w)),
                    fmaxf(fmaxf(v1.x, v1.y), fmaxf(v1.z, v1.w)));
#pragma unroll
    for (int o = 16; o; o >>= 1) m = fmaxf(m, __shfl_xor_sync(0xffffffffu, m, o));

    float s = expf(v0.x - m) + expf(v0.y - m) + expf(v0.z - m) + expf(v0.w - m)
            + expf(v1.x - m) + expf(v1.y - m) + expf(v1.z - m) + expf(v1.w - m);
#pragma unroll
    for (int o = 16; o; o >>= 1) s += __shfl_xor_sync(0xffffffffu, s, o);

    const float lse = m + logf(s);
    v0.x -= lse; v0.y -= lse; v0.z -= lse; v0.w -= lse;
    v1.x -= lse; v1.y -= lse; v1.z -= lse; v1.w -= lse;
    row[lane] = v0;
    row[lane + 32] = v1;
}

// --------- Sinkhorn column pass.  MODE 0: inner; 1: final->fp32 out;
// --------- 2: final-> S,S^T bf16 hi/lo pairs                        ---------
template <int MODE>
__global__ void sk_col(float* __restrict__ S, const int* __restrict__ n2,
                       float* __restrict__ out,
                       __nv_bfloat16* __restrict__ Sh, __nv_bfloat16* __restrict__ Sl,
                       __nv_bfloat16* __restrict__ STh, __nv_bfloat16* __restrict__ STl)
{
    const int b = blockIdx.y;
    const int tx = threadIdx.x & 31;
    const int ty = threadIdx.x >> 5;
    const int j = (blockIdx.x << 5) + tx;

    float* base = S + ((long)b << 16);
    float v[32];
#pragma unroll
    for (int r = 0; r < 32; r++) v[r] = base[(ty * 32 + r) * 256 + j];

    float m = -3.4e38f;
#pragma unroll
    for (int r = 0; r < 32; r++) m = fmaxf(m, v[r]);

    __shared__ float red[8][32];
    red[ty][tx] = m;
    __syncthreads();
    float mt = red[0][tx];
#pragma unroll
    for (int k = 1; k < 8; k++) mt = fmaxf(mt, red[k][tx]);

    float s = 0.f;
#pragma unroll
    for (int r = 0; r < 32; r++) s += expf(v[r] - mt);
    __syncthreads();
    red[ty][tx] = s;
    __syncthreads();
    float st = red[0][tx];
#pragma unroll
    for (int k = 1; k < 8; k++) st += red[k][tx];

    const float lse = mt + logf(st);
    const bool cv = j < n2[b];

    if (MODE == 1) {
        float* ob = out + ((long)b << 16);
#pragma unroll
        for (int r = 0; r < 32; r++)
            ob[(ty * 32 + r) * 256 + j] = cv ? expf(v[r] - lse) : 0.f;
    } else if (MODE == 2) {
        const long bb = (long)b << 16;
#pragma unroll
        for (int r = 0; r < 32; r++) {
            const int rg = ty * 32 + r;
            const float e = cv ? expf(v[r] - lse) : 0.f;
            const __nv_bfloat16 h = __float2bfloat16(e);
            const __nv_bfloat16 l = __float2bfloat16(e - __bfloat162float(h));
            Sh[bb + rg * 256 + j] = h;
            Sl[bb + rg * 256 + j] = l;
            STh[bb + (long)j * 256 + rg] = h;
            STl[bb + (long)j * 256 + rg] = l;
        }
    } else {
        if (cv) {
#pragma unroll
            for (int r = 0; r < 32; r++) base[(ty * 32 + r) * 256 + j] = v[r] - lse;
        }
    }
}

// ---------------------------- host-side helpers ----------------------------
typedef __nv_bfloat16 bf;

template <int BT, int EPI>
static inline void GM(const bf* Ah, const bf* Al, const bf* Bh, const bf* Bl,
                      float* Cf, bf* Oh, bf* Ol, const float* bias,
                      int M, int N, int K, int batch, int ldB, int ldC,
                      long sA, long sB, long sC,
                      const int* n1 = nullptr, const int* n2 = nullptr)
{
    cudaFuncSetAttribute(gmma<BT, EPI>, cudaFuncAttributeMaxDynamicSharedMemorySize, MM_SMEM);
    dim3 grid(N / 128, M / 128, batch);
    gmma<BT, EPI><<<grid, 256, MM_SMEM>>>(Ah, Al, Bh, Bl, Cf, Oh, Ol, bias,
                                          K, ldB, ldC, sA, sB, sC, n1, n2);
}

static inline void SPLIT(const float* x, bf* hi, bf* lo, long n)
{
    const long n4 = n >> 2;
    split_k<<<(unsigned)((n4 + 255) / 256), 256>>>(x, hi, lo, n4);
}

static inline void TCONV(const float* W, bf* hi, bf* lo, int K, int N)
{
    dim3 grid(N / 32, K / 32);
    tconv_k<<<grid, dim3(32, 8)>>>(W, hi, lo, K, N);
}

extern "C" void kernel_launch(void* const* d_in, const int* in_sizes, int n_in,
                              void* d_out, int out_size)
{
    const float* feat1   = (const float*)d_in[0];
    const float* feat2   = (const float*)d_in[1];
    const float* A1      = (const float*)d_in[2];
    const float* A2      = (const float*)d_in[3];
    const float* g0_aW   = (const float*)d_in[4];
    const float* g0_ab   = (const float*)d_in[5];
    const float* g0_uW   = (const float*)d_in[6];
    const float* g0_ub   = (const float*)d_in[7];
    const float* g1_aW   = (const float*)d_in[8];
    const float* g1_ab   = (const float*)d_in[9];
    const float* g1_uW   = (const float*)d_in[10];
    const float* g1_ub   = (const float*)d_in[11];
    const float* aff0_W  = (const float*)d_in[12];
    const float* aff1_W  = (const float*)d_in[13];
    const float* cross_W = (const float*)d_in[14];
    const float* cross_b = (const float*)d_in[15];
    const int*   n1      = (const int*)d_in[16];
    const int*   n2      = (const int*)d_in[17];
    float*       out     = (float*)d_out;

    float *D1, *D2, *D4, *D5, *S, *cn1, *cn2;
    bf *P0h, *P0l, *P1h, *P1l, *XAh, *XAl, *Xh, *Xl, *E1h, *E1l, *E2h, *E2l;
    bf *AN1h, *AN1l, *AN2h, *AN2l, *Sh, *Sl, *STh, *STl, *WThi, *WTlo;
    cudaGetSymbolAddress((void**)&D1, g_D1);
    cudaGetSymbolAddress((void**)&D2, g_D2);
    cudaGetSymbolAddress((void**)&D4, g_D4);
    cudaGetSymbolAddress((void**)&D5, g_D5);
    cudaGetSymbolAddress((void**)&S, g_S);
    cudaGetSymbolAddress((void**)&cn1, g_cn1);
    cudaGetSymbolAddress((void**)&cn2, g_cn2);
    cudaGetSymbolAddress((void**)&P0h, g_P0h);
    cudaGetSymbolAddress((void**)&P0l, g_P0l);
    cudaGetSymbolAddress((void**)&P1h, g_P1h);
    cudaGetSymbolAddress((void**)&P1l, g_P1l);
    cudaGetSymbolAddress((void**)&XAh, g_XAh);
    cudaGetSymbolAddress((void**)&XAl, g_XAl);
    cudaGetSymbolAddress((void**)&Xh, g_Xh);
    cudaGetSymbolAddress((void**)&Xl, g_Xl);
    cudaGetSymbolAddress((void**)&E1h, g_E1h);
    cudaGetSymbolAddress((void**)&E1l, g_E1l);
    cudaGetSymbolAddress((void**)&E2h, g_E2h);
    cudaGetSymbolAddress((void**)&E2l, g_E2l);
    cudaGetSymbolAddress((void**)&AN1h, g_AN1h);
    cudaGetSymbolAddress((void**)&AN1l, g_AN1l);
    cudaGetSymbolAddress((void**)&AN2h, g_AN2h);
    cudaGetSymbolAddress((void**)&AN2l, g_AN2l);
    cudaGetSymbolAddress((void**)&Sh, g_Sh);
    cudaGetSymbolAddress((void**)&Sl, g_Sl);
    cudaGetSymbolAddress((void**)&STh, g_STh);
    cudaGetSymbolAddress((void**)&STl, g_STl);
    cudaGetSymbolAddress((void**)&WThi, g_WThi);
    cudaGetSymbolAddress((void**)&WTlo, g_WTlo);

    const int IN = 1024, HID = 2048;
    const int M = 16384;          // B*N
    const long sNN = 65536;       // 256*256
    const long sNH = 524288;      // 256*2048

    const long o_g0a = 0, o_g0u = 2097152, o_g1a = 4194304, o_g1u = 8388608;
    const long o_af0 = 12582912, o_af1 = 16777216, o_cT = 20971520, o_cB = 25165824;

    // ---- prep ----
    TCONV(g0_aW, WThi + o_g0a, WTlo + o_g0a, IN, HID);
    TCONV(g0_uW, WThi + o_g0u, WTlo + o_g0u, IN, HID);
    TCONV(g1_aW, WThi + o_g1a, WTlo + o_g1a, HID, HID);
    TCONV(g1_uW, WThi + o_g1u, WTlo + o_g1u, HID, HID);
    TCONV(aff0_W, WThi + o_af0, WTlo + o_af0, HID, HID);
    TCONV(aff1_W, WThi + o_af1, WTlo + o_af1, HID, HID);
    TCONV(cross_W, WThi + o_cT, WTlo + o_cT, HID, HID);
    TCONV(cross_W + (long)HID * HID, WThi + o_cB, WTlo + o_cB, HID, HID);

    colsum_k<<<64, 256>>>(A1, cn1);
    colsum_k<<<64, 256>>>(A2, cn2);
    ansplit_k<<<64, 256>>>(A1, cn1, AN1h, AN1l);
    ansplit_k<<<64, 256>>>(A2, cn2, AN2h, AN2l);

    // ---- layer 0, graph 1 ----
    SPLIT(feat1, P0h, P0l, (long)M * IN);
    GM<0, EP_SPLIT_BIAS_RELU>(P0h, P0l, WThi + o_g0a, WTlo + o_g0a, nullptr, XAh, XAl,
                              g0_ab, M, HID, IN, 1, 0, HID, 0, 0, 0);
    GM<0, EP_F32_BIAS_RELU>(P0h, P0l, WThi + o_g0u, WTlo + o_g0u, D1, nullptr, nullptr,
                            g0_ub, M, HID, IN, 1, 0, HID, 0, 0, 0);
    GM<1, EP_SPLIT_ACCUM>(AN1h, AN1l, XAh, XAl, D1, E1h, E1l, nullptr,
                          256, HID, 256, 64, HID, HID, sNN, sNH, sNH);

    // ---- layer 0, graph 2 ----
    SPLIT(feat2, P0h, P0l, (long)M * IN);
    GM<0, EP_SPLIT_BIAS_RELU>(P0h, P0l, WThi + o_g0a, WTlo + o_g0a, nullptr, XAh, XAl,
                              g0_ab, M, HID, IN, 1, 0, HID, 0, 0, 0);
    GM<0, EP_F32_BIAS_RELU>(P0h, P0l, WThi + o_g0u, WTlo + o_g0u, D2, nullptr, nullptr,
                            g0_ub, M, HID, IN, 1, 0, HID, 0, 0, 0);
    GM<1, EP_SPLIT_ACCUM>(AN2h, AN2l, XAh, XAl, D2, E2h, E2l, nullptr,
                          256, HID, 256, 64, HID, HID, sNN, sNH, sNH);

    // ---- affinity 0 + Sinkhorn 1 (emits S, S^T bf16 pairs) ----
    GM<0, EP_SPLIT>(E1h, E1l, WThi + o_af0, WTlo + o_af0, nullptr, Xh, Xl, nullptr,
                    M, HID, HID, 1, 0, HID, 0, 0, 0);
    GM<0, EP_F32_MASK>(Xh, Xl, E2h, E2l, S, nullptr, nullptr, nullptr,
                       256, 256, HID, 64, 0, 256, sNH, sNH, sNN, n1, n2);
    for (int it = 0; it < 10; ++it) {
        if (!(it & 1))    sk_row<<<2048, 256>>>(S, n1);
        else if (it == 9) sk_col<2><<<dim3(8, 64), 256>>>(S, n2, nullptr, Sh, Sl, STh, STl);
        else              sk_col<0><<<dim3(8, 64), 256>>>(S, n2, nullptr, nullptr, nullptr, nullptr, nullptr);
    }

    // ---- cross-graph update ----
    // new_emb1 = emb1@cWtop + (S@emb2)@cWbot + b -> P0 pair
    GM<1, EP_SPLIT>(Sh, Sl, E2h, E2l, nullptr, Xh, Xl, nullptr,
                    256, HID, 256, 64, HID, HID, sNN, sNH, sNH);
    GM<0, EP_F32_BIAS>(E1h, E1l, WThi + o_cT, WTlo + o_cT, D4, nullptr, nullptr,
                       cross_b, M, HID, HID, 1, 0, HID, 0, 0, 0);
    GM<0, EP_SPLIT_ACCUM>(Xh, Xl, WThi + o_cB, WTlo + o_cB, D4, P0h, P0l, nullptr,
                          M, HID, HID, 1, 0, HID, 0, 0, 0);
    // new_emb2 = emb2@cWtop + (S^T@emb1)@cWbot + b -> P1 pair
    GM<1, EP_SPLIT>(STh, STl, E1h, E1l, nullptr, Xh, Xl, nullptr,
                    256, HID, 256, 64, HID, HID, sNN, sNH, sNH);
    GM<0, EP_F32_BIAS>(E2h, E2l, WThi + o_cT, WTlo + o_cT, D5, nullptr, nullptr,
                       cross_b, M, HID, HID, 1, 0, HID, 0, 0, 0);
    GM<0, EP_SPLIT_ACCUM>(Xh, Xl, WThi + o_cB, WTlo + o_cB, D5, P1h, P1l, nullptr,
                          M, HID, HID, 1, 0, HID, 0, 0, 0);

    // ---- layer 1, graph 1 ----
    GM<0, EP_SPLIT_BIAS_RELU>(P0h, P0l, WThi + o_g1a, WTlo + o_g1a, nullptr, XAh, XAl,
                              g1_ab, M, HID, HID, 1, 0, HID, 0, 0, 0);
    GM<0, EP_F32_BIAS_RELU>(P0h, P0l, WThi + o_g1u, WTlo + o_g1u, D1, nullptr, nullptr,
                            g1_ub, M, HID, HID, 1, 0, HID, 0, 0, 0);
    GM<1, EP_SPLIT_ACCUM>(AN1h, AN1l, XAh, XAl, D1, E1h, E1l, nullptr,
                          256, HID, 256, 64, HID, HID, sNN, sNH, sNH);

    // ---- layer 1, graph 2 ----
    GM<0, EP_SPLIT_BIAS_RELU>(P1h, P1l, WThi + o_g1a, WTlo + o_g1a, nullptr, XAh, XAl,
                              g1_ab, M, HID, HID, 1, 0, HID, 0, 0, 0);
    GM<0, EP_F32_BIAS_RELU>(P1h, P1l, WThi + o_g1u, WTlo + o_g1u, D2, nullptr, nullptr,
                            g1_ub, M, HID, HID, 1, 0, HID, 0, 0, 0);
    GM<1, EP_SPLIT_ACCUM>(AN2h, AN2l, XAh, XAl, D2, E2h, E2l, nullptr,
                          256, HID, 256, 64, HID, HID, sNN, sNH, sNH);

    // ---- affinity 1 + Sinkhorn 2 -> out ----
    GM<0, EP_SPLIT>(E1h, E1l, WThi + o_af1, WTlo + o_af1, nullptr, Xh, Xl, nullptr,
                    M, HID, HID, 1, 0, HID, 0, 0, 0);
    GM<0, EP_F32_MASK>(Xh, Xl, E2h, E2l, S, nullptr, nullptr, nullptr,
                       256, 256, HID, 64, 0, 256, sNH, sNH, sNN, n1, n2);
    for (int it = 0; it < 10; ++it) {
        if (!(it & 1))    sk_row<<<2048, 256>>>(S, n1);
        else if (it == 9) sk_col<1><<<dim3(8, 64), 256>>>(S, n2, out, nullptr, nullptr, nullptr, nullptr);
        else              sk_col<0><<<dim3(8, 64), 256>>>(S, n2, nullptr, nullptr, nullptr, nullptr, nullptr);
    }
}